// round 1
// baseline (speedup 1.0000x reference)
#include <cuda_runtime.h>
#include <math.h>

// Problem dims (fixed by the reference)
#define BB 32
#define TT 2048
#define DK 512     // D_IN
#define HH 512     // H
#define MM (BB*TT) // 65536 rows

// Scratch (device globals — allocation-free per harness rules)
__device__ float g_z[(size_t)MM * HH];      // 128 MB
__device__ float g_ht[(size_t)MM * HH];     // 128 MB
__device__ float g_invtau[MM];              // 256 KB

// ---------------------------------------------------------------------------
// Kernel 1: inv_tau[m] = 1 / (1 + softplus(alpha) * sigmoid(w*mm + b))
// ---------------------------------------------------------------------------
__global__ void tau_kernel(const float* __restrict__ motion_mag,
                           const float* __restrict__ w,
                           const float* __restrict__ b,
                           const float* __restrict__ alpha)
{
    int i = blockIdx.x * blockDim.x + threadIdx.x;
    if (i >= MM) return;
    float a  = alpha[0];
    // softplus, overflow-safe
    float sp = (a > 20.f) ? a : log1pf(expf(a));
    float t  = w[0] * motion_mag[i] + b[0];
    float s  = 1.f / (1.f + expf(-t));
    g_invtau[i] = 1.f / (1.f + sp * s);
}

// ---------------------------------------------------------------------------
// Kernel 2: tiled fp32 GEMM  C[m][n] = sum_k X[m][k] * W[n][k]  (+ epilogue)
//   GATE=true : g_z  = sigmoid((C + bz) * inv_tau[m])
//   GATE=false: g_ht = C + bh
// Tiles: BM=128, BN=128, BK=16, 256 threads, 8x8 per-thread accumulators.
// ---------------------------------------------------------------------------
#define BM 128
#define BN 128
#define BKK 16

template<bool GATE>
__global__ __launch_bounds__(256, 2)
void gemm_ep_kernel(const float* __restrict__ X,
                    const float* __restrict__ W,
                    const float* __restrict__ bias)
{
    __shared__ float As[BKK][BM + 4];
    __shared__ float Bs[BKK][BN + 4];

    const int tid = threadIdx.x;
    const int m0  = blockIdx.x * BM;
    const int n0  = blockIdx.y * BN;

    // loader mapping: each thread loads 8 contiguous floats (2x float4)
    const int lr = tid >> 1;          // 0..127 : tile row
    const int lc = (tid & 1) * 8;     // 0 or 8 : k offset

    const int tx = tid & 15;          // 0..15
    const int ty = tid >> 4;          // 0..15
    const int tmb = ty * 8;
    const int tnb = tx * 8;

    float acc[8][8];
    #pragma unroll
    for (int i = 0; i < 8; i++)
        #pragma unroll
        for (int j = 0; j < 8; j++)
            acc[i][j] = 0.f;

    for (int k0 = 0; k0 < DK; k0 += BKK) {
        // load A tile (transposed into As[k][m])
        {
            const float4* Ag = reinterpret_cast<const float4*>(
                X + (size_t)(m0 + lr) * DK + k0 + lc);
            float4 a0 = Ag[0];
            float4 a1 = Ag[1];
            As[lc + 0][lr] = a0.x; As[lc + 1][lr] = a0.y;
            As[lc + 2][lr] = a0.z; As[lc + 3][lr] = a0.w;
            As[lc + 4][lr] = a1.x; As[lc + 5][lr] = a1.y;
            As[lc + 6][lr] = a1.z; As[lc + 7][lr] = a1.w;
        }
        // load B tile (W rows n0+lr)
        {
            const float4* Bg = reinterpret_cast<const float4*>(
                W + (size_t)(n0 + lr) * DK + k0 + lc);
            float4 b0 = Bg[0];
            float4 b1 = Bg[1];
            Bs[lc + 0][lr] = b0.x; Bs[lc + 1][lr] = b0.y;
            Bs[lc + 2][lr] = b0.z; Bs[lc + 3][lr] = b0.w;
            Bs[lc + 4][lr] = b1.x; Bs[lc + 5][lr] = b1.y;
            Bs[lc + 6][lr] = b1.z; Bs[lc + 7][lr] = b1.w;
        }
        __syncthreads();

        #pragma unroll
        for (int kk = 0; kk < BKK; kk++) {
            float ar[8], br[8];
            #pragma unroll
            for (int i = 0; i < 8; i++) ar[i] = As[kk][tmb + i];
            #pragma unroll
            for (int j = 0; j < 8; j++) br[j] = Bs[kk][tnb + j];
            #pragma unroll
            for (int i = 0; i < 8; i++)
                #pragma unroll
                for (int j = 0; j < 8; j++)
                    acc[i][j] = fmaf(ar[i], br[j], acc[i][j]);
        }
        __syncthreads();
    }

    // epilogue
    float* out = GATE ? g_z : g_ht;
    #pragma unroll
    for (int i = 0; i < 8; i++) {
        const int m = m0 + tmb + i;
        float it = GATE ? g_invtau[m] : 0.f;
        #pragma unroll
        for (int j = 0; j < 8; j++) {
            const int n = n0 + tnb + j;
            float v = acc[i][j] + bias[n];
            if (GATE) {
                v = 1.f / (1.f + expf(-v * it));
            }
            out[(size_t)m * HH + n] = v;
        }
    }
}

// ---------------------------------------------------------------------------
// Kernel 3: sequential minGRU scan per (b,h) chain
//   h = h + z*(ht - h); out[b][t][h] = h
// 16384 chains, unrolled x4 for load-level parallelism.
// ---------------------------------------------------------------------------
__global__ void scan_kernel(float* __restrict__ out)
{
    const int idx = blockIdx.x * blockDim.x + threadIdx.x; // 0..16383
    const int b = idx / HH;
    const int h = idx % HH;
    size_t p = (size_t)b * TT * HH + h;

    const float* __restrict__ zg  = g_z;
    const float* __restrict__ hg  = g_ht;

    float hv = 0.f;
    #pragma unroll 1
    for (int t = 0; t < TT; t += 4) {
        // issue 8 independent loads up front (MLP)
        float z0 = zg[p];
        float a0 = hg[p];
        float z1 = zg[p + HH];
        float a1 = hg[p + HH];
        float z2 = zg[p + 2 * HH];
        float a2 = hg[p + 2 * HH];
        float z3 = zg[p + 3 * HH];
        float a3 = hg[p + 3 * HH];

        hv = fmaf(z0, a0 - hv, hv); out[p]          = hv;
        hv = fmaf(z1, a1 - hv, hv); out[p + HH]     = hv;
        hv = fmaf(z2, a2 - hv, hv); out[p + 2 * HH] = hv;
        hv = fmaf(z3, a3 - hv, hv); out[p + 3 * HH] = hv;
        p += 4 * HH;
    }
}

// ---------------------------------------------------------------------------
// Launch
// ---------------------------------------------------------------------------
extern "C" void kernel_launch(void* const* d_in, const int* in_sizes, int n_in,
                              void* d_out, int out_size)
{
    const float* x      = (const float*)d_in[0];
    const float* mmg    = (const float*)d_in[1];
    const float* Wz     = (const float*)d_in[2];
    const float* bz     = (const float*)d_in[3];
    const float* Wh     = (const float*)d_in[4];
    const float* bh     = (const float*)d_in[5];
    const float* mw     = (const float*)d_in[6];
    const float* mb     = (const float*)d_in[7];
    const float* alpha  = (const float*)d_in[8];
    float* out          = (float*)d_out;

    // 1) gate temperature
    tau_kernel<<<(MM + 255) / 256, 256>>>(mmg, mw, mb, alpha);

    // 2) two fused GEMMs
    dim3 grid(MM / BM, HH / BN);   // (512, 4)
    gemm_ep_kernel<true ><<<grid, 256>>>(x, Wz, bz);
    gemm_ep_kernel<false><<<grid, 256>>>(x, Wh, bh);

    // 3) sequential scan
    scan_kernel<<<(BB * HH) / 128, 128>>>(out);
}

// round 3
// speedup vs baseline: 2.7592x; 2.7592x over previous
#include <cuda_runtime.h>
#include <cstdint>
#include <math.h>

// Problem dims (fixed)
#define BB 32
#define TT 2048
#define DK 512
#define HH 512
#define MM (BB*TT)   // 65536

// Scratch
__device__ float g_z [(size_t)MM * HH];
__device__ float g_ht[(size_t)MM * HH];
__device__ float g_invtau[MM];

// ---------------------------------------------------------------------------
// helpers
// ---------------------------------------------------------------------------
__device__ __forceinline__ uint32_t smem_u32(const void* p) {
    uint32_t a;
    asm("{ .reg .u64 t; cvta.to.shared.u64 t, %1; cvt.u32.u64 %0, t; }"
        : "=r"(a) : "l"(p));
    return a;
}
__device__ __forceinline__ uint32_t f2tf32(float x) {
    uint32_t r; asm("cvt.rna.tf32.f32 %0, %1;" : "=r"(r) : "f"(x)); return r;
}
__device__ __forceinline__ void ldsm4(uint32_t (&r)[4], uint32_t addr) {
    asm volatile("ldmatrix.sync.aligned.m8n8.x4.shared.b16 {%0,%1,%2,%3}, [%4];"
        : "=r"(r[0]), "=r"(r[1]), "=r"(r[2]), "=r"(r[3]) : "r"(addr));
}
__device__ __forceinline__ void mma_tf32(float (&d)[4], const uint32_t (&a)[4],
                                         uint32_t b0, uint32_t b1) {
    asm volatile(
        "mma.sync.aligned.m16n8k8.row.col.f32.tf32.tf32.f32 "
        "{%0,%1,%2,%3}, {%4,%5,%6,%7}, {%8,%9}, {%0,%1,%2,%3};"
        : "+f"(d[0]), "+f"(d[1]), "+f"(d[2]), "+f"(d[3])
        : "r"(a[0]), "r"(a[1]), "r"(a[2]), "r"(a[3]), "r"(b0), "r"(b1));
}
#define STS128U(addr, v0, v1, v2, v3)                                         \
    asm volatile("st.shared.v4.b32 [%0], {%1,%2,%3,%4};"                      \
                 :: "r"(addr), "r"(v0), "r"(v1), "r"(v2), "r"(v3) : "memory")

// ---------------------------------------------------------------------------
// Kernel 1: inv_tau
// ---------------------------------------------------------------------------
__global__ void tau_kernel(const float* __restrict__ motion_mag,
                           const float* __restrict__ w,
                           const float* __restrict__ b,
                           const float* __restrict__ alpha)
{
    int i = blockIdx.x * blockDim.x + threadIdx.x;
    if (i >= MM) return;
    float a  = alpha[0];
    float sp = (a > 20.f) ? a : log1pf(expf(a));
    float t  = w[0] * motion_mag[i] + b[0];
    float s  = 1.f / (1.f + expf(-t));
    g_invtau[i] = 1.f / (1.f + sp * s);
}

// ---------------------------------------------------------------------------
// Kernel 2: tf32 mma.sync GEMM.
//   C[m][n] = sum_k X[m][k] * W[n][k], BM=128, BN=256, BK=32, 512 threads.
//   Warp grid 2(m) x 8(n); warp tile 64x32 = 16 m16n8k8 mma per k-step.
//   A in smem [m][k] rows of 128B (SW128 xor swizzle), B [n][k] same.
//   Fragments loaded with ldmatrix.x4.b16 (tf32 = b16 pair).
// ---------------------------------------------------------------------------
template<bool GATE>
__global__ __launch_bounds__(512)
void gemm_mma(const float* __restrict__ X,
              const float* __restrict__ W,
              const float* __restrict__ bias)
{
    __shared__ uint32_t sA[128 * 32];   // 16 KB
    __shared__ uint32_t sB[256 * 32];   // 32 KB

    const int tid  = threadIdx.x;
    const int lane = tid & 31;
    const int wid  = tid >> 5;
    const int warp_m = wid & 1;        // 0..1
    const int warp_n = wid >> 1;       // 0..7
    const int m0 = blockIdx.x * 128;
    const int n0 = blockIdx.y * 256;

    const uint32_t sAaddr = smem_u32(sA);
    const uint32_t sBaddr = smem_u32(sB);

    // ---- loader mapping ----
    const int a_row = tid >> 2;              // 0..127
    const int a_c   = (tid & 3) * 2;         // 16B-chunk base {0,2,4,6}
    const int b_row = tid >> 1;              // 0..255
    const int b_c   = (tid & 1) * 4;         // {0,4}

    const float4* Arow = (const float4*)(X + (size_t)(m0 + a_row) * DK);
    const float4* Brow = (const float4*)(W + (size_t)(n0 + b_row) * DK);

    uint32_t a_sts[2], b_sts[4];
    #pragma unroll
    for (int j = 0; j < 2; j++)
        a_sts[j] = sAaddr + (uint32_t)(a_row * 128 + (((a_c + j) ^ (a_row & 7)) << 4));
    #pragma unroll
    for (int j = 0; j < 4; j++)
        b_sts[j] = sBaddr + (uint32_t)(b_row * 128 + (((b_c + j) ^ (b_row & 7)) << 4));

    // ---- fragment ldmatrix addresses ----
    const int lr15 = lane & 15;
    const int hi   = lane >> 4;       // 0/1 -> second 16B chunk
    const int swz  = lane & 7;
    const uint32_t a_base = sAaddr + (uint32_t)((warp_m * 64 + lr15) * 128);
    const uint32_t b_base = sBaddr + (uint32_t)((warp_n * 32 + lr15) * 128);

    float acc[4][4][4];
    #pragma unroll
    for (int i = 0; i < 4; i++)
        #pragma unroll
        for (int j = 0; j < 4; j++)
            #pragma unroll
            for (int q = 0; q < 4; q++)
                acc[i][j][q] = 0.f;

    float4 pa[2], pb[4];
    // prefetch chunk 0
    #pragma unroll
    for (int j = 0; j < 2; j++) pa[j] = Arow[a_c + j];
    #pragma unroll
    for (int j = 0; j < 4; j++) pb[j] = Brow[b_c + j];

    for (int ch = 0; ch < 16; ++ch) {
        __syncthreads();
        #pragma unroll
        for (int j = 0; j < 2; j++)
            STS128U(a_sts[j], f2tf32(pa[j].x), f2tf32(pa[j].y),
                              f2tf32(pa[j].z), f2tf32(pa[j].w));
        #pragma unroll
        for (int j = 0; j < 4; j++)
            STS128U(b_sts[j], f2tf32(pb[j].x), f2tf32(pb[j].y),
                              f2tf32(pb[j].z), f2tf32(pb[j].w));
        __syncthreads();

        if (ch < 15) {
            const int f4 = (ch + 1) * 8;
            #pragma unroll
            for (int j = 0; j < 2; j++) pa[j] = Arow[f4 + a_c + j];
            #pragma unroll
            for (int j = 0; j < 4; j++) pb[j] = Brow[f4 + b_c + j];
        }

        #pragma unroll
        for (int ks = 0; ks < 4; ks++) {
            const uint32_t xoff = (uint32_t)(((ks * 2 + hi) ^ swz) << 4);
            uint32_t af[4][4], bf[2][4];
            #pragma unroll
            for (int mt = 0; mt < 4; mt++)
                ldsm4(af[mt], a_base + mt * 2048 + xoff);
            #pragma unroll
            for (int p = 0; p < 2; p++)
                ldsm4(bf[p], b_base + p * 2048 + xoff);
            // bf[p] = {b0(nt=2p), b0(nt=2p+1), b1(nt=2p), b1(nt=2p+1)}
            #pragma unroll
            for (int mt = 0; mt < 4; mt++) {
                #pragma unroll
                for (int p = 0; p < 2; p++) {
                    mma_tf32(acc[mt][2*p+0], af[mt], bf[p][0], bf[p][2]);
                    mma_tf32(acc[mt][2*p+1], af[mt], bf[p][1], bf[p][3]);
                }
            }
        }
    }

    // ---- epilogue ----
    float* out = GATE ? g_z : g_ht;
    #pragma unroll
    for (int mt = 0; mt < 4; mt++) {
        const int m  = m0 + warp_m * 64 + mt * 16 + (lane >> 2);
        const float it0 = GATE ? g_invtau[m]     : 0.f;
        const float it1 = GATE ? g_invtau[m + 8] : 0.f;
        #pragma unroll
        for (int nt = 0; nt < 4; nt++) {
            const int n = n0 + warp_n * 32 + nt * 8 + (lane & 3) * 2;
            const float bs0 = bias[n];
            const float bs1 = bias[n + 1];
            float v0 = acc[mt][nt][0] + bs0;
            float v1 = acc[mt][nt][1] + bs1;
            float v2 = acc[mt][nt][2] + bs0;
            float v3 = acc[mt][nt][3] + bs1;
            if (GATE) {
                v0 = 1.f / (1.f + expf(-v0 * it0));
                v1 = 1.f / (1.f + expf(-v1 * it0));
                v2 = 1.f / (1.f + expf(-v2 * it1));
                v3 = 1.f / (1.f + expf(-v3 * it1));
            }
            *(float2*)(out + (size_t)m * HH + n)       = make_float2(v0, v1);
            *(float2*)(out + (size_t)(m + 8) * HH + n) = make_float2(v2, v3);
        }
    }
}

// ---------------------------------------------------------------------------
// Kernel 3: scan, unroll 16 for deep MLP
// ---------------------------------------------------------------------------
__global__ void scan_kernel(float* __restrict__ out)
{
    const int idx = blockIdx.x * blockDim.x + threadIdx.x; // 0..16383
    const int b = idx >> 9;
    const int h = idx & 511;
    size_t p = (size_t)b * TT * HH + h;

    float hv = 0.f;
    #pragma unroll 1
    for (int t = 0; t < TT; t += 16) {
        float z[16], a[16];
        #pragma unroll
        for (int u = 0; u < 16; u++) {
            z[u] = g_z [p + (size_t)u * HH];
            a[u] = g_ht[p + (size_t)u * HH];
        }
        #pragma unroll
        for (int u = 0; u < 16; u++) {
            hv = fmaf(z[u], a[u] - hv, hv);
            out[p + (size_t)u * HH] = hv;
        }
        p += (size_t)16 * HH;
    }
}

// ---------------------------------------------------------------------------
// Launch
// ---------------------------------------------------------------------------
extern "C" void kernel_launch(void* const* d_in, const int* in_sizes, int n_in,
                              void* d_out, int out_size)
{
    const float* x     = (const float*)d_in[0];
    const float* mmg   = (const float*)d_in[1];
    const float* Wz    = (const float*)d_in[2];
    const float* bz    = (const float*)d_in[3];
    const float* Wh    = (const float*)d_in[4];
    const float* bh    = (const float*)d_in[5];
    const float* mw    = (const float*)d_in[6];
    const float* mb    = (const float*)d_in[7];
    const float* alpha = (const float*)d_in[8];
    float* out         = (float*)d_out;

    tau_kernel<<<(MM + 255) / 256, 256>>>(mmg, mw, mb, alpha);

    dim3 grid(MM / 128, HH / 256);   // (512, 2)
    gemm_mma<true ><<<grid, 512>>>(x, Wz, bz);
    gemm_mma<false><<<grid, 512>>>(x, Wh, bh);

    scan_kernel<<<(BB * HH) / 128, 128>>>(out);
}

// round 4
// speedup vs baseline: 3.0975x; 1.1226x over previous
#include <cuda_runtime.h>
#include <cstdint>
#include <math.h>

// Problem dims (fixed)
#define BB 32
#define TT 2048
#define DK 512
#define HH 512
#define MM (BB*TT)   // 65536

// Scan chunking
#define CH 16
#define CL (TT/CH)   // 128
#define NCHAIN (BB*HH)  // 16384

// Scratch
__device__ float g_z [(size_t)MM * HH];
__device__ float g_ht[(size_t)MM * HH];
__device__ float g_invtau[MM];
__device__ float g_cB [CH * NCHAIN];
__device__ float g_cP [CH * NCHAIN];
__device__ float g_hin[CH * NCHAIN];

// ---------------------------------------------------------------------------
// helpers
// ---------------------------------------------------------------------------
__device__ __forceinline__ uint32_t smem_u32(const void* p) {
    uint32_t a;
    asm("{ .reg .u64 t; cvta.to.shared.u64 t, %1; cvt.u32.u64 %0, t; }"
        : "=r"(a) : "l"(p));
    return a;
}
__device__ __forceinline__ uint32_t f2tf32(float x) {
    uint32_t r; asm("cvt.rna.tf32.f32 %0, %1;" : "=r"(r) : "f"(x)); return r;
}
__device__ __forceinline__ void ldsm4(uint32_t (&r)[4], uint32_t addr) {
    asm volatile("ldmatrix.sync.aligned.m8n8.x4.shared.b16 {%0,%1,%2,%3}, [%4];"
        : "=r"(r[0]), "=r"(r[1]), "=r"(r[2]), "=r"(r[3]) : "r"(addr));
}
__device__ __forceinline__ void mma_tf32(float (&d)[4], const uint32_t (&a)[4],
                                         uint32_t b0, uint32_t b1) {
    asm volatile(
        "mma.sync.aligned.m16n8k8.row.col.f32.tf32.tf32.f32 "
        "{%0,%1,%2,%3}, {%4,%5,%6,%7}, {%8,%9}, {%0,%1,%2,%3};"
        : "+f"(d[0]), "+f"(d[1]), "+f"(d[2]), "+f"(d[3])
        : "r"(a[0]), "r"(a[1]), "r"(a[2]), "r"(a[3]), "r"(b0), "r"(b1));
}
#define STS128U(addr, v0, v1, v2, v3)                                         \
    asm volatile("st.shared.v4.b32 [%0], {%1,%2,%3,%4};"                      \
                 :: "r"(addr), "r"(v0), "r"(v1), "r"(v2), "r"(v3) : "memory")

// ---------------------------------------------------------------------------
// Kernel 1: inv_tau
// ---------------------------------------------------------------------------
__global__ void tau_kernel(const float* __restrict__ motion_mag,
                           const float* __restrict__ w,
                           const float* __restrict__ b,
                           const float* __restrict__ alpha)
{
    int i = blockIdx.x * blockDim.x + threadIdx.x;
    if (i >= MM) return;
    float a  = alpha[0];
    float sp = (a > 20.f) ? a : log1pf(expf(a));
    float t  = w[0] * motion_mag[i] + b[0];
    float s  = 1.f / (1.f + expf(-t));
    g_invtau[i] = 1.f / (1.f + sp * s);
}

// ---------------------------------------------------------------------------
// Kernel 2: fused tf32 GEMM (both Wz and Wh in one kernel).
//   grid (4, 512): x<2 -> Wz (gate), x>=2 -> Wh. 4 adjacent bids share the
//   same X m-tile -> X read once from DRAM, W (2MB) stays in L2.
//   BM=128, BN=256, BK=32, 512 threads, warp grid 2(m) x 8(n), 64x32/warp.
//   Double-buffered dynamic SMEM (2 x 48KB), one __syncthreads per chunk.
// ---------------------------------------------------------------------------
#define A_WORDS (128 * 32)            // per stage
#define B_WORDS (256 * 32)
#define STAGE_BYTES ((A_WORDS + B_WORDS) * 4)   // 49152
#define GEMM_SMEM (2 * STAGE_BYTES)             // 98304

__global__ __launch_bounds__(512, 1)
void gemm_fused(const float* __restrict__ X,
                const float* __restrict__ Wz,
                const float* __restrict__ bz,
                const float* __restrict__ Wh,
                const float* __restrict__ bh)
{
    extern __shared__ uint32_t dsm[];
    const uint32_t sb = smem_u32(dsm);

    const int tid  = threadIdx.x;
    const int lane = tid & 31;
    const int wid  = tid >> 5;
    const int warp_m = wid & 1;
    const int warp_n = wid >> 1;

    const bool GATE = (blockIdx.x < 2);
    const float* W    = GATE ? Wz : Wh;
    const float* bias = GATE ? bz : bh;
    const int n0 = (blockIdx.x & 1) * 256;
    const int m0 = blockIdx.y * 128;

    // ---- loader mapping ----
    const int a_row = tid >> 2;              // 0..127
    const int a_c   = (tid & 3) * 2;         // {0,2,4,6}
    const int b_row = tid >> 1;              // 0..255
    const int b_c   = (tid & 1) * 4;         // {0,4}

    const float4* Arow = (const float4*)(X + (size_t)(m0 + a_row) * DK);
    const float4* Brow = (const float4*)(W + (size_t)(n0 + b_row) * DK);

    uint32_t a_sts[2], b_sts[4];
    #pragma unroll
    for (int j = 0; j < 2; j++)
        a_sts[j] = sb + (uint32_t)(a_row * 128 + (((a_c + j) ^ (a_row & 7)) << 4));
    #pragma unroll
    for (int j = 0; j < 4; j++)
        b_sts[j] = sb + (uint32_t)(A_WORDS * 4 + b_row * 128
                                   + (((b_c + j) ^ (b_row & 7)) << 4));

    // ---- fragment ldmatrix bases ----
    const int lr15 = lane & 15;
    const int hi   = lane >> 4;
    const int swz  = lane & 7;
    const uint32_t a_base = sb + (uint32_t)((warp_m * 64 + lr15) * 128);
    const uint32_t b_base = sb + (uint32_t)(A_WORDS * 4 + (warp_n * 32 + lr15) * 128);

    float acc[4][4][4];
    #pragma unroll
    for (int i = 0; i < 4; i++)
        #pragma unroll
        for (int j = 0; j < 4; j++)
            #pragma unroll
            for (int q = 0; q < 4; q++)
                acc[i][j][q] = 0.f;

    float4 pa[2], pb[4];
    #pragma unroll
    for (int j = 0; j < 2; j++) pa[j] = Arow[a_c + j];
    #pragma unroll
    for (int j = 0; j < 4; j++) pb[j] = Brow[b_c + j];
    // stage 0 fill
    #pragma unroll
    for (int j = 0; j < 2; j++)
        STS128U(a_sts[j], f2tf32(pa[j].x), f2tf32(pa[j].y),
                          f2tf32(pa[j].z), f2tf32(pa[j].w));
    #pragma unroll
    for (int j = 0; j < 4; j++)
        STS128U(b_sts[j], f2tf32(pb[j].x), f2tf32(pb[j].y),
                          f2tf32(pb[j].z), f2tf32(pb[j].w));
    __syncthreads();

    for (int ch = 0; ch < 16; ++ch) {
        const uint32_t cs = (uint32_t)(ch & 1) * STAGE_BYTES;
        const uint32_t ns = (uint32_t)((ch + 1) & 1) * STAGE_BYTES;

        if (ch < 15) {
            const int f4 = (ch + 1) * 8;
            #pragma unroll
            for (int j = 0; j < 2; j++) pa[j] = Arow[f4 + a_c + j];
            #pragma unroll
            for (int j = 0; j < 4; j++) pb[j] = Brow[f4 + b_c + j];
        }

        #pragma unroll
        for (int ks = 0; ks < 4; ks++) {
            const uint32_t xoff = (uint32_t)(((ks * 2 + hi) ^ swz) << 4);
            uint32_t af[4][4], bf[2][4];
            #pragma unroll
            for (int mt = 0; mt < 4; mt++)
                ldsm4(af[mt], a_base + cs + mt * 2048 + xoff);
            #pragma unroll
            for (int p = 0; p < 2; p++)
                ldsm4(bf[p], b_base + cs + p * 2048 + xoff);
            #pragma unroll
            for (int mt = 0; mt < 4; mt++) {
                #pragma unroll
                for (int p = 0; p < 2; p++) {
                    mma_tf32(acc[mt][2*p+0], af[mt], bf[p][0], bf[p][2]);
                    mma_tf32(acc[mt][2*p+1], af[mt], bf[p][1], bf[p][3]);
                }
            }
        }

        if (ch < 15) {
            #pragma unroll
            for (int j = 0; j < 2; j++)
                STS128U(a_sts[j] + ns, f2tf32(pa[j].x), f2tf32(pa[j].y),
                                       f2tf32(pa[j].z), f2tf32(pa[j].w));
            #pragma unroll
            for (int j = 0; j < 4; j++)
                STS128U(b_sts[j] + ns, f2tf32(pb[j].x), f2tf32(pb[j].y),
                                       f2tf32(pb[j].z), f2tf32(pb[j].w));
            __syncthreads();
        }
    }

    // ---- epilogue ----
    float* out = GATE ? g_z : g_ht;
    #pragma unroll
    for (int mt = 0; mt < 4; mt++) {
        const int m  = m0 + warp_m * 64 + mt * 16 + (lane >> 2);
        const float it0 = GATE ? g_invtau[m]     : 0.f;
        const float it1 = GATE ? g_invtau[m + 8] : 0.f;
        #pragma unroll
        for (int nt = 0; nt < 4; nt++) {
            const int n = n0 + warp_n * 32 + nt * 8 + (lane & 3) * 2;
            const float bs0 = bias[n];
            const float bs1 = bias[n + 1];
            float v0 = acc[mt][nt][0] + bs0;
            float v1 = acc[mt][nt][1] + bs1;
            float v2 = acc[mt][nt][2] + bs0;
            float v3 = acc[mt][nt][3] + bs1;
            if (GATE) {
                v0 = 1.f / (1.f + expf(-v0 * it0));
                v1 = 1.f / (1.f + expf(-v1 * it0));
                v2 = 1.f / (1.f + expf(-v2 * it1));
                v3 = 1.f / (1.f + expf(-v3 * it1));
            }
            *(float2*)(out + (size_t)m * HH + n)       = make_float2(v0, v1);
            *(float2*)(out + (size_t)(m + 8) * HH + n) = make_float2(v2, v3);
        }
    }
}

// ---------------------------------------------------------------------------
// Kernel 3a: per-chunk local scan (h_in = 0) -> carry (B, P)
//   idx: c = idx>>14 in [0,15), chain bh = idx & 16383. Coalesced over h.
// ---------------------------------------------------------------------------
__global__ void scan_p1()
{
    const int idx = blockIdx.x * blockDim.x + threadIdx.x; // 0 .. 15*16384-1
    const int bh = idx & (NCHAIN - 1);
    const int c  = idx >> 14;           // 0..14
    const int b  = bh >> 9;
    const int h  = bh & 511;
    size_t p = ((size_t)b * TT + (size_t)c * CL) * HH + h;

    float hv = 0.f, P = 1.f;
    #pragma unroll 1
    for (int t = 0; t < CL; t += 8) {
        float z[8], a[8];
        #pragma unroll
        for (int u = 0; u < 8; u++) {
            z[u] = g_z [p + (size_t)u * HH];
            a[u] = g_ht[p + (size_t)u * HH];
        }
        #pragma unroll
        for (int u = 0; u < 8; u++) {
            hv = fmaf(z[u], a[u] - hv, hv);
            P *= (1.f - z[u]);
        }
        p += (size_t)8 * HH;
    }
    g_cB[(size_t)c * NCHAIN + bh] = hv;
    g_cP[(size_t)c * NCHAIN + bh] = P;
}

// ---------------------------------------------------------------------------
// Kernel 3b: compose chunk carries sequentially (tiny)
// ---------------------------------------------------------------------------
__global__ void scan_p2()
{
    const int bh = blockIdx.x * blockDim.x + threadIdx.x; // 0..16383
    float hv = 0.f;
    #pragma unroll
    for (int c = 0; c < CH; c++) {
        g_hin[(size_t)c * NCHAIN + bh] = hv;
        if (c < CH - 1)
            hv = fmaf(g_cP[(size_t)c * NCHAIN + bh], hv,
                      g_cB[(size_t)c * NCHAIN + bh]);
    }
}

// ---------------------------------------------------------------------------
// Kernel 3c: final per-chunk scan with correct h_in, writes output
// ---------------------------------------------------------------------------
__global__ void scan_p3(float* __restrict__ out)
{
    const int idx = blockIdx.x * blockDim.x + threadIdx.x; // 0 .. 16*16384-1
    const int bh = idx & (NCHAIN - 1);
    const int c  = idx >> 14;           // 0..15
    const int b  = bh >> 9;
    const int h  = bh & 511;
    size_t p = ((size_t)b * TT + (size_t)c * CL) * HH + h;

    float hv = g_hin[(size_t)c * NCHAIN + bh];
    #pragma unroll 1
    for (int t = 0; t < CL; t += 8) {
        float z[8], a[8];
        #pragma unroll
        for (int u = 0; u < 8; u++) {
            z[u] = g_z [p + (size_t)u * HH];
            a[u] = g_ht[p + (size_t)u * HH];
        }
        #pragma unroll
        for (int u = 0; u < 8; u++) {
            hv = fmaf(z[u], a[u] - hv, hv);
            out[p + (size_t)u * HH] = hv;
        }
        p += (size_t)8 * HH;
    }
}

// ---------------------------------------------------------------------------
// Launch
// ---------------------------------------------------------------------------
extern "C" void kernel_launch(void* const* d_in, const int* in_sizes, int n_in,
                              void* d_out, int out_size)
{
    const float* x     = (const float*)d_in[0];
    const float* mmg   = (const float*)d_in[1];
    const float* Wz    = (const float*)d_in[2];
    const float* bz    = (const float*)d_in[3];
    const float* Wh    = (const float*)d_in[4];
    const float* bh    = (const float*)d_in[5];
    const float* mw    = (const float*)d_in[6];
    const float* mb    = (const float*)d_in[7];
    const float* alpha = (const float*)d_in[8];
    float* out         = (float*)d_out;

    cudaFuncSetAttribute(gemm_fused, cudaFuncAttributeMaxDynamicSharedMemorySize,
                         GEMM_SMEM);

    tau_kernel<<<(MM + 255) / 256, 256>>>(mmg, mw, mb, alpha);

    dim3 grid(4, MM / 128);   // x: {Wz n0=0, Wz n0=256, Wh n0=0, Wh n0=256}
    gemm_fused<<<grid, 512, GEMM_SMEM>>>(x, Wz, bz, Wh, bh);

    scan_p1<<<(15 * NCHAIN) / 256, 256>>>();
    scan_p2<<<NCHAIN / 256, 256>>>();
    scan_p3<<<(CH * NCHAIN) / 256, 256>>>(out);
}

// round 5
// speedup vs baseline: 5.2664x; 1.7002x over previous
#include <cuda_runtime.h>
#include <cuda_fp16.h>
#include <cstdint>
#include <math.h>

// Problem dims (fixed)
#define BB 32
#define TT 2048
#define DK 512
#define HH 512
#define MM (BB*TT)   // 65536

// Scan chunking
#define CH 16
#define CL (TT/CH)   // 128
#define NCHAIN (BB*HH)  // 16384

// Scratch
__device__ float g_z [(size_t)MM * HH];
__device__ float g_ht[(size_t)MM * HH];
__device__ float g_invtau[MM];
__device__ float g_cB [CH * NCHAIN];
__device__ float g_cP [CH * NCHAIN];
__device__ float g_hin[CH * NCHAIN];
__device__ __align__(16) __half g_x16[(size_t)MM * DK];   // 64 MB
__device__ __align__(16) __half g_w16[2 * HH * DK];       // Wz then Wh

// ---------------------------------------------------------------------------
// helpers
// ---------------------------------------------------------------------------
__device__ __forceinline__ uint32_t smem_u32(const void* p) {
    uint32_t a;
    asm("{ .reg .u64 t; cvta.to.shared.u64 t, %1; cvt.u32.u64 %0, t; }"
        : "=r"(a) : "l"(p));
    return a;
}
__device__ __forceinline__ uint32_t packh2(float lo, float hi) {
    uint32_t r;
    asm("cvt.rn.f16x2.f32 %0, %1, %2;" : "=r"(r) : "f"(hi), "f"(lo));
    return r;
}
__device__ __forceinline__ void ldsm4(uint32_t (&r)[4], uint32_t addr) {
    asm volatile("ldmatrix.sync.aligned.m8n8.x4.shared.b16 {%0,%1,%2,%3}, [%4];"
        : "=r"(r[0]), "=r"(r[1]), "=r"(r[2]), "=r"(r[3]) : "r"(addr));
}
__device__ __forceinline__ void mma_f16(float (&d)[4], const uint32_t (&a)[4],
                                        uint32_t b0, uint32_t b1) {
    asm volatile(
        "mma.sync.aligned.m16n8k16.row.col.f32.f16.f16.f32 "
        "{%0,%1,%2,%3}, {%4,%5,%6,%7}, {%8,%9}, {%0,%1,%2,%3};"
        : "+f"(d[0]), "+f"(d[1]), "+f"(d[2]), "+f"(d[3])
        : "r"(a[0]), "r"(a[1]), "r"(a[2]), "r"(a[3]), "r"(b0), "r"(b1));
}
__device__ __forceinline__ void cp16(uint32_t saddr, const void* gptr) {
    asm volatile("cp.async.cg.shared.global [%0], [%1], 16;"
                 :: "r"(saddr), "l"(__cvta_generic_to_global(gptr)));
}
#define CP_COMMIT() asm volatile("cp.async.commit_group;" ::: "memory")
#define CP_WAIT2()  asm volatile("cp.async.wait_group 2;" ::: "memory")

// ---------------------------------------------------------------------------
// Kernel 0a: tau  (also tiny)
// ---------------------------------------------------------------------------
__global__ void tau_kernel(const float* __restrict__ motion_mag,
                           const float* __restrict__ w,
                           const float* __restrict__ b,
                           const float* __restrict__ alpha)
{
    int i = blockIdx.x * blockDim.x + threadIdx.x;
    if (i >= MM) return;
    float a  = alpha[0];
    float sp = (a > 20.f) ? a : log1pf(expf(a));
    float t  = w[0] * motion_mag[i] + b[0];
    float s  = 1.f / (1.f + expf(-t));
    g_invtau[i] = 1.f / (1.f + sp * s);
}

// ---------------------------------------------------------------------------
// Kernel 0b/0c: fp32 -> fp16 conversion (8 floats / thread)
// ---------------------------------------------------------------------------
__global__ void cvt_x(const float4* __restrict__ X)
{
    const int i = blockIdx.x * blockDim.x + threadIdx.x; // < MM*DK/8
    float4 a = X[2 * i];
    float4 b = X[2 * i + 1];
    uint4 o;
    o.x = packh2(a.x, a.y); o.y = packh2(a.z, a.w);
    o.z = packh2(b.x, b.y); o.w = packh2(b.z, b.w);
    ((uint4*)g_x16)[i] = o;
}
__global__ void cvt_w(const float4* __restrict__ Wz, const float4* __restrict__ Wh)
{
    const int i = blockIdx.x * blockDim.x + threadIdx.x; // < 2*HH*DK/8
    const int half_n = HH * DK / 8;
    const float4* src = (i < half_n) ? Wz : Wh;
    const int j = (i < half_n) ? i : i - half_n;
    float4 a = src[2 * j];
    float4 b = src[2 * j + 1];
    uint4 o;
    o.x = packh2(a.x, a.y); o.y = packh2(a.z, a.w);
    o.z = packh2(b.x, b.y); o.w = packh2(b.z, b.w);
    ((uint4*)g_w16)[i] = o;
}

// ---------------------------------------------------------------------------
// Kernel 2: fused fp16 GEMM (Wz + Wh), cp.async 4-stage pipeline.
//   grid (4, 512): x = {z|n0=0, z|n0=256, h|n0=0, h|n0=256}; y = m-tile.
//   BM=128, BN=256, BK=64 fp16, 512 threads, warp 2(m) x 8(n), tile 64x32.
// ---------------------------------------------------------------------------
#define A_BYTES 16384                 // 128 rows x 128B
#define B_BYTES 32768                 // 256 rows x 128B
#define STAGE_BYTES (A_BYTES + B_BYTES)
#define NST 4
#define GEMM_SMEM (NST * STAGE_BYTES) // 196608
#define NCHUNK 8

__global__ __launch_bounds__(512, 1)
void gemm_fused(const float* __restrict__ bz, const float* __restrict__ bh)
{
    extern __shared__ uint32_t dsm[];
    const uint32_t sb = smem_u32(dsm);

    const int tid  = threadIdx.x;
    const int lane = tid & 31;
    const int wid  = tid >> 5;
    const int warp_m = wid & 1;
    const int warp_n = wid >> 1;

    const bool GATE = (blockIdx.x < 2);
    const __half* W16  = g_w16 + (GATE ? 0 : (size_t)HH * DK);
    const float* bias  = GATE ? bz : bh;
    const int n0 = (blockIdx.x & 1) * 256;
    const int m0 = blockIdx.y * 128;

    // ---- cp.async loader mapping: thread -> (row group, 16B chunk) ----
    const int lrow = tid >> 3;   // 0..63
    const int lc   = tid & 7;    // 16B chunk in 128B row
    const uint32_t asw = (uint32_t)(((lc ^ (lrow & 7)) << 4));

    // per-stage-relative smem offsets (row-dependent swizzle differs by +64 rows:
    // (lrow+64)&7 == lrow&7, so swizzle identical for all row groups)
    // A rows: lrow, lrow+64 ; B rows: lrow, +64, +128, +192
    const __half* Xrow0 = g_x16 + (size_t)(m0 + lrow) * DK + lc * 8;
    const __half* Wrow0 = W16  + (size_t)(n0 + lrow) * DK + lc * 8;

    // ---- fragment ldmatrix bases (stage-relative) ----
    const int lr15 = lane & 15;
    const int hi   = lane >> 4;
    const int swz  = lane & 7;
    const uint32_t a_rel = (uint32_t)((warp_m * 64 + lr15) * 128);
    const uint32_t b_rel = (uint32_t)(A_BYTES + (warp_n * 32 + lr15) * 128);

    float acc[4][4][4];
    #pragma unroll
    for (int i = 0; i < 4; i++)
        #pragma unroll
        for (int j = 0; j < 4; j++)
            #pragma unroll
            for (int q = 0; q < 4; q++)
                acc[i][j][q] = 0.f;

    // ---- issue one stage ----
    auto load_stage = [&](int ch, int s) {
        const uint32_t sA = sb + (uint32_t)s * STAGE_BYTES;
        const uint32_t sB = sA + A_BYTES;
        const int koff = ch * 64;   // fp16 elements
        #pragma unroll
        for (int j = 0; j < 2; j++)
            cp16(sA + (uint32_t)(lrow + 64 * j) * 128 + asw,
                 Xrow0 + (size_t)(64 * j) * DK + koff);
        #pragma unroll
        for (int j = 0; j < 4; j++)
            cp16(sB + (uint32_t)(lrow + 64 * j) * 128 + asw,
                 Wrow0 + (size_t)(64 * j) * DK + koff);
    };

    // prologue: stages 0..2
    #pragma unroll
    for (int s = 0; s < 3; s++) { load_stage(s, s); CP_COMMIT(); }

    for (int ch = 0; ch < NCHUNK; ++ch) {
        CP_WAIT2();          // stage ch complete (<=2 groups pending)
        __syncthreads();     // data visible to all; all warps done with mma(ch-1)

        if (ch + 3 < NCHUNK) load_stage(ch + 3, (ch + 3) & 3);
        CP_COMMIT();

        const uint32_t sbase = sb + (uint32_t)(ch & 3) * STAGE_BYTES;
        const uint32_t a_base = sbase + a_rel;
        const uint32_t b_base = sbase + b_rel;

        #pragma unroll
        for (int ks = 0; ks < 4; ks++) {
            const uint32_t xoff = (uint32_t)(((ks * 2 + hi) ^ swz) << 4);
            uint32_t af[4][4], bf[2][4];
            #pragma unroll
            for (int mt = 0; mt < 4; mt++)
                ldsm4(af[mt], a_base + mt * 2048 + xoff);
            #pragma unroll
            for (int p = 0; p < 2; p++)
                ldsm4(bf[p], b_base + p * 2048 + xoff);
            #pragma unroll
            for (int mt = 0; mt < 4; mt++) {
                #pragma unroll
                for (int p = 0; p < 2; p++) {
                    mma_f16(acc[mt][2*p+0], af[mt], bf[p][0], bf[p][2]);
                    mma_f16(acc[mt][2*p+1], af[mt], bf[p][1], bf[p][3]);
                }
            }
        }
    }

    // ---- epilogue ----
    float* out = GATE ? g_z : g_ht;
    #pragma unroll
    for (int mt = 0; mt < 4; mt++) {
        const int m  = m0 + warp_m * 64 + mt * 16 + (lane >> 2);
        const float it0 = GATE ? g_invtau[m]     : 0.f;
        const float it1 = GATE ? g_invtau[m + 8] : 0.f;
        #pragma unroll
        for (int nt = 0; nt < 4; nt++) {
            const int n = n0 + warp_n * 32 + nt * 8 + (lane & 3) * 2;
            const float bs0 = bias[n];
            const float bs1 = bias[n + 1];
            float v0 = acc[mt][nt][0] + bs0;
            float v1 = acc[mt][nt][1] + bs1;
            float v2 = acc[mt][nt][2] + bs0;
            float v3 = acc[mt][nt][3] + bs1;
            if (GATE) {
                v0 = 1.f / (1.f + expf(-v0 * it0));
                v1 = 1.f / (1.f + expf(-v1 * it0));
                v2 = 1.f / (1.f + expf(-v2 * it1));
                v3 = 1.f / (1.f + expf(-v3 * it1));
            }
            *(float2*)(out + (size_t)m * HH + n)       = make_float2(v0, v1);
            *(float2*)(out + (size_t)(m + 8) * HH + n) = make_float2(v2, v3);
        }
    }
}

// ---------------------------------------------------------------------------
// Kernel 3a: per-chunk local scan (h_in = 0) -> carry (B, P)
// ---------------------------------------------------------------------------
__global__ void scan_p1()
{
    const int idx = blockIdx.x * blockDim.x + threadIdx.x;
    const int bh = idx & (NCHAIN - 1);
    const int c  = idx >> 14;           // 0..14
    const int b  = bh >> 9;
    const int h  = bh & 511;
    size_t p = ((size_t)b * TT + (size_t)c * CL) * HH + h;

    float hv = 0.f, P = 1.f;
    #pragma unroll 1
    for (int t = 0; t < CL; t += 8) {
        float z[8], a[8];
        #pragma unroll
        for (int u = 0; u < 8; u++) {
            z[u] = g_z [p + (size_t)u * HH];
            a[u] = g_ht[p + (size_t)u * HH];
        }
        #pragma unroll
        for (int u = 0; u < 8; u++) {
            hv = fmaf(z[u], a[u] - hv, hv);
            P *= (1.f - z[u]);
        }
        p += (size_t)8 * HH;
    }
    g_cB[(size_t)c * NCHAIN + bh] = hv;
    g_cP[(size_t)c * NCHAIN + bh] = P;
}

// ---------------------------------------------------------------------------
// Kernel 3b: compose chunk carries (prefetch all, then sequential)
// ---------------------------------------------------------------------------
__global__ void scan_p2()
{
    const int bh = blockIdx.x * blockDim.x + threadIdx.x; // 0..16383
    float cb[CH - 1], cp[CH - 1];
    #pragma unroll
    for (int c = 0; c < CH - 1; c++) {
        cb[c] = g_cB[(size_t)c * NCHAIN + bh];
        cp[c] = g_cP[(size_t)c * NCHAIN + bh];
    }
    float hv = 0.f;
    #pragma unroll
    for (int c = 0; c < CH; c++) {
        g_hin[(size_t)c * NCHAIN + bh] = hv;
        if (c < CH - 1) hv = fmaf(cp[c], hv, cb[c]);
    }
}

// ---------------------------------------------------------------------------
// Kernel 3c: final per-chunk scan with correct h_in, writes output
// ---------------------------------------------------------------------------
__global__ void scan_p3(float* __restrict__ out)
{
    const int idx = blockIdx.x * blockDim.x + threadIdx.x;
    const int bh = idx & (NCHAIN - 1);
    const int c  = idx >> 14;           // 0..15
    const int b  = bh >> 9;
    const int h  = bh & 511;
    size_t p = ((size_t)b * TT + (size_t)c * CL) * HH + h;

    float hv = g_hin[(size_t)c * NCHAIN + bh];
    #pragma unroll 1
    for (int t = 0; t < CL; t += 8) {
        float z[8], a[8];
        #pragma unroll
        for (int u = 0; u < 8; u++) {
            z[u] = g_z [p + (size_t)u * HH];
            a[u] = g_ht[p + (size_t)u * HH];
        }
        #pragma unroll
        for (int u = 0; u < 8; u++) {
            hv = fmaf(z[u], a[u] - hv, hv);
            out[p + (size_t)u * HH] = hv;
        }
        p += (size_t)8 * HH;
    }
}

// ---------------------------------------------------------------------------
// Launch
// ---------------------------------------------------------------------------
extern "C" void kernel_launch(void* const* d_in, const int* in_sizes, int n_in,
                              void* d_out, int out_size)
{
    const float* x     = (const float*)d_in[0];
    const float* mmg   = (const float*)d_in[1];
    const float* Wz    = (const float*)d_in[2];
    const float* bz    = (const float*)d_in[3];
    const float* Wh    = (const float*)d_in[4];
    const float* bh    = (const float*)d_in[5];
    const float* mw    = (const float*)d_in[6];
    const float* mb    = (const float*)d_in[7];
    const float* alpha = (const float*)d_in[8];
    float* out         = (float*)d_out;

    cudaFuncSetAttribute(gemm_fused, cudaFuncAttributeMaxDynamicSharedMemorySize,
                         GEMM_SMEM);

    tau_kernel<<<(MM + 255) / 256, 256>>>(mmg, mw, mb, alpha);
    cvt_x<<<(MM * DK / 8) / 256, 256>>>((const float4*)x);
    cvt_w<<<(2 * HH * DK / 8) / 256, 256>>>((const float4*)Wz, (const float4*)Wh);

    dim3 grid(4, MM / 128);
    gemm_fused<<<grid, 512, GEMM_SMEM>>>(bz, bh);

    scan_p1<<<(15 * NCHAIN) / 256, 256>>>();
    scan_p2<<<NCHAIN / 256, 256>>>();
    scan_p3<<<(CH * NCHAIN) / 256, 256>>>(out);
}